// round 3
// baseline (speedup 1.0000x reference)
#include <cuda_runtime.h>

// Problem constants
#define Bn     8192
#define Tb     16        // batch rows per block (full chain held in smem)
#define F0n    2048
#define En     512
#define OUTn   2048
#define Wn     3584      // F0 + 3*E
#define NNZ_E  8192
#define NNZ_M  16384
#define NBLK   (Bn / Tb) // 512
#define NTHR   512

// ---------------------------------------------------------------------------
// Device scratch (no allocation allowed)
// ---------------------------------------------------------------------------
__device__ int  g_ptr[4 * 2049];
__device__ int2 g_ent[4 * 16384];   // packed {col, float_bits(val)}, CSR order

// ---------------------------------------------------------------------------
// CSR build: one block per weight (3 embed + main). smem count/scan/scatter.
// ---------------------------------------------------------------------------
__global__ void build_k(const int* __restrict__ r0, const int* __restrict__ c0, const float* __restrict__ v0,
                        const int* __restrict__ r1, const int* __restrict__ c1, const float* __restrict__ v1,
                        const int* __restrict__ r2, const int* __restrict__ c2, const float* __restrict__ v2,
                        const int* __restrict__ rm, const int* __restrict__ cm, const float* __restrict__ vm) {
    __shared__ int cnt[2048];
    __shared__ int cur[2048];
    __shared__ int part[512];
    int w = blockIdx.x;
    int t = threadIdx.x;

    const int*   rows = (w == 0) ? r0 : (w == 1) ? r1 : (w == 2) ? r2 : rm;
    const int*   cols = (w == 0) ? c0 : (w == 1) ? c1 : (w == 2) ? c2 : cm;
    const float* vals = (w == 0) ? v0 : (w == 1) ? v1 : (w == 2) ? v2 : vm;
    int nrows = (w < 3) ? En : OUTn;
    int nnz   = (w < 3) ? NNZ_E : NNZ_M;
    int per   = nrows / NTHR;            // 1 or 4

    for (int i = t; i < 2048; i += NTHR) cnt[i] = 0;
    __syncthreads();
    for (int k = t; k < nnz; k += NTHR) atomicAdd(&cnt[rows[k]], 1);
    __syncthreads();

    int sum = 0;
    for (int j = 0; j < per; j++) sum += cnt[t * per + j];
    part[t] = sum;
    __syncthreads();
    for (int off = 1; off < NTHR; off <<= 1) {      // Hillis-Steele inclusive
        int v = (t >= off) ? part[t - off] : 0;
        __syncthreads();
        part[t] += v;
        __syncthreads();
    }
    int run = part[t] - sum;                         // exclusive prefix
    for (int j = 0; j < per; j++) {
        int i = t * per + j;
        g_ptr[w * 2049 + i] = run;
        cur[i] = run;
        run += cnt[i];
    }
    if (t == NTHR - 1) g_ptr[w * 2049 + nrows] = part[NTHR - 1];
    __syncthreads();

    for (int k = t; k < nnz; k += NTHR) {
        int p = atomicAdd(&cur[rows[k]], 1);
        g_ent[w * 16384 + p] = make_int2(cols[k], __float_as_int(vals[k]));
    }
}

// ---------------------------------------------------------------------------
// Fused chain kernel. Block owns batch tile of Tb=16 rows; the whole feature
// vector h[16][3584] lives in smem (XOR-b swizzled to avoid bank conflicts).
//   smem: h   = 16*3584 floats (229376 B)
//         stg = 32*17 floats for transposed MAIN write-out (2176 B)
// Warp layout: 2 groups of 16 lanes; group owns one CSR row, lane owns one b.
// ---------------------------------------------------------------------------
#define SMEM_BYTES (Tb * Wn * 4 + 32 * 17 * 4)

__global__ void __launch_bounds__(NTHR, 1) fused_k(const float* __restrict__ x,
                                                   float* __restrict__ out) {
    extern __shared__ float sh[];
    float* stg = sh + Tb * Wn;

    int t    = threadIdx.x;
    int wid  = t >> 5;
    int lane = t & 31;
    int g    = lane >> 4;       // row-group within warp
    int b    = lane & 15;       // batch row within tile
    int b0   = blockIdx.x * Tb;

    // ---- load x tile, swizzled batch-major: h[b][f ^ b] ----
    const float* xb = x + (size_t)b0 * F0n;
    for (int i = t; i < Tb * (F0n / 4); i += NTHR) {
        int br = i >> 9;                 // /(F0n/4)
        int f4 = (i & 511) * 4;
        float4 v = *reinterpret_cast<const float4*>(xb + (size_t)br * F0n + f4);
        float* hb = sh + br * Wn;
        hb[(f4 + 0) ^ br] = v.x;
        hb[(f4 + 1) ^ br] = v.y;
        hb[(f4 + 2) ^ br] = v.z;
        hb[(f4 + 3) ^ br] = v.w;
    }
    __syncthreads();

    float* hb = sh + b * Wn;

    // ---- three embed levels ----
    for (int lev = 0; lev < 3; lev++) {
        int fo = F0n + lev * En;
        const int*  lptr = g_ptr + lev * 2049;
        const int2* ent  = g_ent + lev * 16384;
        for (int pr = 0; pr < 16; pr++) {
            int r = wid * 32 + pr * 2 + g;
            int s = __ldg(lptr + r);
            int e = __ldg(lptr + r + 1);
            float acc = 0.f;
            int k = s;
            for (; k + 4 <= e; k += 4) {          // MLP-4 against L2 latency
                int2 a0 = __ldg(ent + k);
                int2 a1 = __ldg(ent + k + 1);
                int2 a2 = __ldg(ent + k + 2);
                int2 a3 = __ldg(ent + k + 3);
                acc += __int_as_float(a0.y) * hb[a0.x ^ b];
                acc += __int_as_float(a1.y) * hb[a1.x ^ b];
                acc += __int_as_float(a2.y) * hb[a2.x ^ b];
                acc += __int_as_float(a3.y) * hb[a3.x ^ b];
            }
            for (; k < e; k++) {
                int2 a = __ldg(ent + k);
                acc += __int_as_float(a.y) * hb[a.x ^ b];
            }
            hb[(fo + r) ^ b] = acc;
        }
        __syncthreads();
    }

    // ---- MAIN, in 32-row chunks staged through smem for coalesced writes ----
    const int*  mptr = g_ptr + 3 * 2049;
    const int2* ment = g_ent + 3 * 16384;
    for (int ch = 0; ch < OUTn / 32; ch++) {
        int rl = wid * 2 + g;               // 0..31 within chunk
        int r  = ch * 32 + rl;
        int s = __ldg(mptr + r);
        int e = __ldg(mptr + r + 1);
        float acc = 0.f;
        int k = s;
        for (; k + 4 <= e; k += 4) {
            int2 a0 = __ldg(ment + k);
            int2 a1 = __ldg(ment + k + 1);
            int2 a2 = __ldg(ment + k + 2);
            int2 a3 = __ldg(ment + k + 3);
            acc += __int_as_float(a0.y) * hb[a0.x ^ b];
            acc += __int_as_float(a1.y) * hb[a1.x ^ b];
            acc += __int_as_float(a2.y) * hb[a2.x ^ b];
            acc += __int_as_float(a3.y) * hb[a3.x ^ b];
        }
        for (; k < e; k++) {
            int2 a = __ldg(ment + k);
            acc += __int_as_float(a.y) * hb[a.x ^ b];
        }
        stg[rl * 17 + b] = acc;
        __syncthreads();
        // coalesced transposed write: lane-consecutive r for fixed b
        {
            int bw = t >> 5;                // 0..15
            int rw = t & 31;                // 0..31
            out[(size_t)(b0 + bw) * OUTn + ch * 32 + rw] = stg[rw * 17 + bw];
        }
        __syncthreads();
    }
}

// ---------------------------------------------------------------------------
// Launch
// ---------------------------------------------------------------------------
extern "C" void kernel_launch(void* const* d_in, const int* in_sizes, int n_in,
                              void* d_out, int out_size) {
    const float* x   = (const float*)d_in[0];
    const int*   er0 = (const int*)d_in[1];
    const int*   ec0 = (const int*)d_in[2];
    const float* ev0 = (const float*)d_in[3];
    const int*   er1 = (const int*)d_in[4];
    const int*   ec1 = (const int*)d_in[5];
    const float* ev1 = (const float*)d_in[6];
    const int*   er2 = (const int*)d_in[7];
    const int*   ec2 = (const int*)d_in[8];
    const float* ev2 = (const float*)d_in[9];
    const int*   mr  = (const int*)d_in[10];
    const int*   mc  = (const int*)d_in[11];
    const float* mv  = (const float*)d_in[12];
    float* out = (float*)d_out;

    static int attr_done = 0;
    if (!attr_done) {
        cudaFuncSetAttribute(fused_k, cudaFuncAttributeMaxDynamicSharedMemorySize,
                             SMEM_BYTES);
        attr_done = 1;
    }

    build_k<<<4, NTHR>>>(er0, ec0, ev0, er1, ec1, ev1, er2, ec2, ev2, mr, mc, mv);
    fused_k<<<NBLK, NTHR, SMEM_BYTES>>>(x, out);
}

// round 4
// speedup vs baseline: 1.3071x; 1.3071x over previous
#include <cuda_runtime.h>

// Problem constants
#define Bn     8192
#define Tb     16        // batch rows per block (full chain held in smem)
#define F0n    2048
#define En     512
#define OUTn   2048
#define Wn     3584      // F0 + 3*E
#define NNZ_E  8192
#define NNZ_M  16384
#define NBLK   (Bn / Tb) // 512
#define NTHR   1024      // 32 warps

// ---------------------------------------------------------------------------
// Device scratch (no allocation allowed)
// ---------------------------------------------------------------------------
__device__ int  g_ptr[4 * 2049];
__device__ int2 g_ent[4 * 16384];   // packed {col, float_bits(val)}, CSR order

// ---------------------------------------------------------------------------
// CSR build: one block per weight (3 embed + main). smem count/scan/scatter.
// ---------------------------------------------------------------------------
#define BLD 512
__global__ void build_k(const int* __restrict__ r0, const int* __restrict__ c0, const float* __restrict__ v0,
                        const int* __restrict__ r1, const int* __restrict__ c1, const float* __restrict__ v1,
                        const int* __restrict__ r2, const int* __restrict__ c2, const float* __restrict__ v2,
                        const int* __restrict__ rm, const int* __restrict__ cm, const float* __restrict__ vm) {
    __shared__ int cnt[2048];
    __shared__ int cur[2048];
    __shared__ int part[BLD];
    int w = blockIdx.x;
    int t = threadIdx.x;

    const int*   rows = (w == 0) ? r0 : (w == 1) ? r1 : (w == 2) ? r2 : rm;
    const int*   cols = (w == 0) ? c0 : (w == 1) ? c1 : (w == 2) ? c2 : cm;
    const float* vals = (w == 0) ? v0 : (w == 1) ? v1 : (w == 2) ? v2 : vm;
    int nrows = (w < 3) ? En : OUTn;
    int nnz   = (w < 3) ? NNZ_E : NNZ_M;
    int per   = nrows / BLD;             // 1 or 4

    for (int i = t; i < 2048; i += BLD) cnt[i] = 0;
    __syncthreads();
    for (int k = t; k < nnz; k += BLD) atomicAdd(&cnt[rows[k]], 1);
    __syncthreads();

    int sum = 0;
    for (int j = 0; j < per; j++) sum += cnt[t * per + j];
    part[t] = sum;
    __syncthreads();
    for (int off = 1; off < BLD; off <<= 1) {       // Hillis-Steele inclusive
        int v = (t >= off) ? part[t - off] : 0;
        __syncthreads();
        part[t] += v;
        __syncthreads();
    }
    int run = part[t] - sum;                         // exclusive prefix
    for (int j = 0; j < per; j++) {
        int i = t * per + j;
        g_ptr[w * 2049 + i] = run;
        cur[i] = run;
        run += cnt[i];
    }
    if (t == BLD - 1) g_ptr[w * 2049 + nrows] = part[BLD - 1];
    __syncthreads();

    for (int k = t; k < nnz; k += BLD) {
        int p = atomicAdd(&cur[rows[k]], 1);
        g_ent[w * 16384 + p] = make_int2(cols[k], __float_as_int(vals[k]));
    }
}

// ---------------------------------------------------------------------------
// Fused chain kernel, v2.
// Block = 16 batch rows; h[16][3584] in smem (XOR-b swizzle). 32 warps.
// Every warp works ONE CSR row at a time, warp-uniform:
//   lane -> (b = lane&15, kh = lane>>4); half kh processes entries s+kh, s+kh+2,...
//   combine halves with shfl_xor(.,16); half 0 writes the result.
// ---------------------------------------------------------------------------
#define SMEM_BYTES (Tb * Wn * 4 + 32 * 17 * 4)

__global__ void __launch_bounds__(NTHR, 1) fused_k(const float* __restrict__ x,
                                                   float* __restrict__ out) {
    extern __shared__ float sh[];
    float* stg = sh + Tb * Wn;          // [32][17] transpose staging

    int t    = threadIdx.x;
    int wid  = t >> 5;                  // 0..31
    int lane = t & 31;
    int kh   = lane >> 4;               // entry-stream half
    int b    = lane & 15;               // batch row within tile
    int b0   = blockIdx.x * Tb;

    // ---- load x tile, swizzled batch-major: h[b][f ^ b] ----
    const float* xb = x + (size_t)b0 * F0n;
    for (int i = t; i < Tb * (F0n / 4); i += NTHR) {
        int br = i >> 9;                 // /(F0n/4)
        int f4 = (i & 511) * 4;
        float4 v = *reinterpret_cast<const float4*>(xb + (size_t)br * F0n + f4);
        float* hr = sh + br * Wn;
        hr[(f4 + 0) ^ br] = v.x;
        hr[(f4 + 1) ^ br] = v.y;
        hr[(f4 + 2) ^ br] = v.z;
        hr[(f4 + 3) ^ br] = v.w;
    }
    __syncthreads();

    float* hb = sh + b * Wn;

    // ---- three embed levels ----
    for (int lev = 0; lev < 3; lev++) {
        int fo = F0n + lev * En;
        const int*  lptr = g_ptr + lev * 2049;
        const int2* ent  = g_ent + lev * 16384;
#pragma unroll 1
        for (int pr = 0; pr < En / 32; pr++) {
            int r = wid * (En / 32) + pr;
            int s = __ldg(lptr + r);
            int e = __ldg(lptr + r + 1);
            float acc = 0.f;
            int k = s + kh;
            for (; k + 6 < e; k += 8) {          // 4 entries in flight per half
                int2 a0 = __ldg(ent + k);
                int2 a1 = __ldg(ent + k + 2);
                int2 a2 = __ldg(ent + k + 4);
                int2 a3 = __ldg(ent + k + 6);
                acc += __int_as_float(a0.y) * hb[a0.x ^ b];
                acc += __int_as_float(a1.y) * hb[a1.x ^ b];
                acc += __int_as_float(a2.y) * hb[a2.x ^ b];
                acc += __int_as_float(a3.y) * hb[a3.x ^ b];
            }
            for (; k < e; k += 2) {
                int2 a = __ldg(ent + k);
                acc += __int_as_float(a.y) * hb[a.x ^ b];
            }
            acc += __shfl_xor_sync(0xffffffffu, acc, 16);
            if (kh == 0) hb[(fo + r) ^ b] = acc;
        }
        __syncthreads();
    }

    // ---- MAIN: warp-uniform rows, 32-row chunks staged for coalesced out ----
    const int*  mptr = g_ptr + 3 * 2049;
    const int2* ment = g_ent + 3 * 16384;
#pragma unroll 1
    for (int ch = 0; ch < OUTn / 32; ch++) {
        int r = ch * 32 + wid;
        int s = __ldg(mptr + r);
        int e = __ldg(mptr + r + 1);
        float acc = 0.f;
        int k = s + kh;
        for (; k + 6 < e; k += 8) {
            int2 a0 = __ldg(ment + k);
            int2 a1 = __ldg(ment + k + 2);
            int2 a2 = __ldg(ment + k + 4);
            int2 a3 = __ldg(ment + k + 6);
            acc += __int_as_float(a0.y) * hb[a0.x ^ b];
            acc += __int_as_float(a1.y) * hb[a1.x ^ b];
            acc += __int_as_float(a2.y) * hb[a2.x ^ b];
            acc += __int_as_float(a3.y) * hb[a3.x ^ b];
        }
        for (; k < e; k += 2) {
            int2 a = __ldg(ment + k);
            acc += __int_as_float(a.y) * hb[a.x ^ b];
        }
        acc += __shfl_xor_sync(0xffffffffu, acc, 16);

        __syncthreads();                    // WAR: prior chunk's stg reads done
        if (kh == 0) stg[wid * 17 + b] = acc;
        __syncthreads();                    // stg visible
        if (t < 512) {
            int bw = t >> 5;                // 0..15
            int rw = t & 31;                // 0..31
            out[(size_t)(b0 + bw) * OUTn + ch * 32 + rw] = stg[rw * 17 + bw];
        }
    }
}

// ---------------------------------------------------------------------------
// Launch
// ---------------------------------------------------------------------------
extern "C" void kernel_launch(void* const* d_in, const int* in_sizes, int n_in,
                              void* d_out, int out_size) {
    const float* x   = (const float*)d_in[0];
    const int*   er0 = (const int*)d_in[1];
    const int*   ec0 = (const int*)d_in[2];
    const float* ev0 = (const float*)d_in[3];
    const int*   er1 = (const int*)d_in[4];
    const int*   ec1 = (const int*)d_in[5];
    const float* ev1 = (const float*)d_in[6];
    const int*   er2 = (const int*)d_in[7];
    const int*   ec2 = (const int*)d_in[8];
    const float* ev2 = (const float*)d_in[9];
    const int*   mr  = (const int*)d_in[10];
    const int*   mc  = (const int*)d_in[11];
    const float* mv  = (const float*)d_in[12];
    float* out = (float*)d_out;

    static int attr_done = 0;
    if (!attr_done) {
        cudaFuncSetAttribute(fused_k, cudaFuncAttributeMaxDynamicSharedMemorySize,
                             SMEM_BYTES);
        attr_done = 1;
    }

    build_k<<<4, BLD>>>(er0, ec0, ev0, er1, ec1, ev1, er2, ec2, ev2, mr, mc, mv);
    fused_k<<<NBLK, NTHR, SMEM_BYTES>>>(x, out);
}

// round 5
// speedup vs baseline: 1.7782x; 1.3604x over previous
#include <cuda_runtime.h>

// Problem constants
#define Bn     8192
#define Tb     16        // batch rows per block (full chain held in smem)
#define F0n    2048
#define En     512
#define OUTn   2048
#define Wn     3584      // F0 + 3*E
#define NNZ_E  8192
#define NNZ_M  16384
#define NBLK   (Bn / Tb) // 512
#define NTHR   1024      // 32 warps

// ---------------------------------------------------------------------------
// Device scratch (no allocation allowed)
// ---------------------------------------------------------------------------
__device__ int  g_ptr[4 * 2049];
__device__ int2 g_ent[4 * 16384];   // packed {col, float_bits(val)}, CSR order

// ---------------------------------------------------------------------------
// CSR build: one block per weight (3 embed + main). smem count/scan/scatter.
// ---------------------------------------------------------------------------
#define BLD 512
__global__ void build_k(const int* __restrict__ r0, const int* __restrict__ c0, const float* __restrict__ v0,
                        const int* __restrict__ r1, const int* __restrict__ c1, const float* __restrict__ v1,
                        const int* __restrict__ r2, const int* __restrict__ c2, const float* __restrict__ v2,
                        const int* __restrict__ rm, const int* __restrict__ cm, const float* __restrict__ vm) {
    __shared__ int cnt[2048];
    __shared__ int cur[2048];
    __shared__ int part[BLD];
    int w = blockIdx.x;
    int t = threadIdx.x;

    const int*   rows = (w == 0) ? r0 : (w == 1) ? r1 : (w == 2) ? r2 : rm;
    const int*   cols = (w == 0) ? c0 : (w == 1) ? c1 : (w == 2) ? c2 : cm;
    const float* vals = (w == 0) ? v0 : (w == 1) ? v1 : (w == 2) ? v2 : vm;
    int nrows = (w < 3) ? En : OUTn;
    int nnz   = (w < 3) ? NNZ_E : NNZ_M;
    int per   = nrows / BLD;             // 1 or 4

    for (int i = t; i < 2048; i += BLD) cnt[i] = 0;
    __syncthreads();
    for (int k = t; k < nnz; k += BLD) atomicAdd(&cnt[rows[k]], 1);
    __syncthreads();

    int sum = 0;
    for (int j = 0; j < per; j++) sum += cnt[t * per + j];
    part[t] = sum;
    __syncthreads();
    for (int off = 1; off < BLD; off <<= 1) {
        int v = (t >= off) ? part[t - off] : 0;
        __syncthreads();
        part[t] += v;
        __syncthreads();
    }
    int run = part[t] - sum;
    for (int j = 0; j < per; j++) {
        int i = t * per + j;
        g_ptr[w * 2049 + i] = run;
        cur[i] = run;
        run += cnt[i];
    }
    if (t == BLD - 1) g_ptr[w * 2049 + nrows] = part[BLD - 1];
    __syncthreads();

    for (int k = t; k < nnz; k += BLD) {
        int p = atomicAdd(&cur[rows[k]], 1);
        g_ent[w * 16384 + p] = make_int2(cols[k], __float_as_int(vals[k]));
    }
}

// ---------------------------------------------------------------------------
// Row-pair accumulator: two CSR rows with interleaved unroll-4 streams.
// Each half (kh=0/1) walks its parity of the entry list.
// ---------------------------------------------------------------------------
__device__ __forceinline__ void row_pair(const int2* __restrict__ ent,
                                         int sA, int eA, int sB, int eB,
                                         const float* __restrict__ hb,
                                         int b, int kh,
                                         float& oA, float& oB) {
    float accA = 0.f, accB = 0.f;
    int kA = sA + kh, kB = sB + kh;
    while (kA + 6 < eA && kB + 6 < eB) {
        int2 a0 = __ldg(ent + kA);
        int2 a1 = __ldg(ent + kA + 2);
        int2 a2 = __ldg(ent + kA + 4);
        int2 a3 = __ldg(ent + kA + 6);
        int2 c0 = __ldg(ent + kB);
        int2 c1 = __ldg(ent + kB + 2);
        int2 c2 = __ldg(ent + kB + 4);
        int2 c3 = __ldg(ent + kB + 6);
        accA += __int_as_float(a0.y) * hb[a0.x ^ b];
        accB += __int_as_float(c0.y) * hb[c0.x ^ b];
        accA += __int_as_float(a1.y) * hb[a1.x ^ b];
        accB += __int_as_float(c1.y) * hb[c1.x ^ b];
        accA += __int_as_float(a2.y) * hb[a2.x ^ b];
        accB += __int_as_float(c2.y) * hb[c2.x ^ b];
        accA += __int_as_float(a3.y) * hb[a3.x ^ b];
        accB += __int_as_float(c3.y) * hb[c3.x ^ b];
        kA += 8; kB += 8;
    }
    while (kA + 6 < eA) {
        int2 a0 = __ldg(ent + kA);
        int2 a1 = __ldg(ent + kA + 2);
        int2 a2 = __ldg(ent + kA + 4);
        int2 a3 = __ldg(ent + kA + 6);
        accA += __int_as_float(a0.y) * hb[a0.x ^ b];
        accA += __int_as_float(a1.y) * hb[a1.x ^ b];
        accA += __int_as_float(a2.y) * hb[a2.x ^ b];
        accA += __int_as_float(a3.y) * hb[a3.x ^ b];
        kA += 8;
    }
    while (kB + 6 < eB) {
        int2 c0 = __ldg(ent + kB);
        int2 c1 = __ldg(ent + kB + 2);
        int2 c2 = __ldg(ent + kB + 4);
        int2 c3 = __ldg(ent + kB + 6);
        accB += __int_as_float(c0.y) * hb[c0.x ^ b];
        accB += __int_as_float(c1.y) * hb[c1.x ^ b];
        accB += __int_as_float(c2.y) * hb[c2.x ^ b];
        accB += __int_as_float(c3.y) * hb[c3.x ^ b];
        kB += 8;
    }
    for (; kA < eA; kA += 2) {
        int2 a = __ldg(ent + kA);
        accA += __int_as_float(a.y) * hb[a.x ^ b];
    }
    for (; kB < eB; kB += 2) {
        int2 c = __ldg(ent + kB);
        accB += __int_as_float(c.y) * hb[c.x ^ b];
    }
    oA = accA; oB = accB;
}

// ---------------------------------------------------------------------------
// Fused chain kernel, v3.
// Block = 16 batch rows; h[16][3584] in smem (XOR-b swizzle). 32 warps.
// lane -> (b = lane&15, kh = lane>>4). Warp-uniform CSR rows, dual-row MLP.
// MAIN: warp owns 64 consecutive rows; register accumulation in 16-row
// groups, shfl-combine, direct coalesced float4 stores. NO barriers in MAIN.
// ---------------------------------------------------------------------------
#define SMEM_BYTES (Tb * Wn * 4)

__global__ void __launch_bounds__(NTHR, 1) fused_k(const float* __restrict__ x,
                                                   float* __restrict__ out) {
    extern __shared__ float sh[];

    int t    = threadIdx.x;
    int wid  = t >> 5;                  // 0..31
    int lane = t & 31;
    int kh   = lane >> 4;               // entry-stream half
    int b    = lane & 15;               // batch row within tile
    int b0   = blockIdx.x * Tb;

    // ---- load x tile, swizzled batch-major: h[b][f ^ b] ----
    const float* xb = x + (size_t)b0 * F0n;
    for (int i = t; i < Tb * (F0n / 4); i += NTHR) {
        int br = i >> 9;                 // /(F0n/4)
        int f4 = (i & 511) * 4;
        float4 v = *reinterpret_cast<const float4*>(xb + (size_t)br * F0n + f4);
        float* hr = sh + br * Wn;
        hr[(f4 + 0) ^ br] = v.x;
        hr[(f4 + 1) ^ br] = v.y;
        hr[(f4 + 2) ^ br] = v.z;
        hr[(f4 + 3) ^ br] = v.w;
    }
    __syncthreads();

    const float* hb = sh + b * Wn;
    float* hbw = sh + b * Wn;

    // ---- three embed levels: 16 rows/warp, processed as 8 pairs ----
    for (int lev = 0; lev < 3; lev++) {
        int fo = F0n + lev * En;
        const int*  lptr = g_ptr + lev * 2049;
        const int2* ent  = g_ent + lev * 16384;
#pragma unroll 1
        for (int pr = 0; pr < 8; pr++) {
            int r = wid * 16 + pr * 2;
            int sA = __ldg(lptr + r);
            int sB = __ldg(lptr + r + 1);   // = eA
            int eB = __ldg(lptr + r + 2);
            float vA, vB;
            row_pair(ent, sA, sB, sB, eB, hb, b, kh, vA, vB);
            vA += __shfl_xor_sync(0xffffffffu, vA, 16);
            vB += __shfl_xor_sync(0xffffffffu, vB, 16);
            if (kh == 0) {
                hbw[(fo + r) ^ b]     = vA;
                hbw[(fo + r + 1) ^ b] = vB;
            }
        }
        __syncthreads();
    }

    // ---- MAIN: warp owns rows [wid*64, wid*64+64), groups of 16, no syncs ----
    const int*  mptr = g_ptr + 3 * 2049;
    const int2* ment = g_ent + 3 * 16384;
    float* outb = out + (size_t)(b0 + b) * OUTn;
#pragma unroll 1
    for (int grp = 0; grp < 4; grp++) {
        int rb = wid * 64 + grp * 16;
        float a[16];
#pragma unroll
        for (int jp = 0; jp < 8; jp++) {
            int r = rb + jp * 2;
            int sA = __ldg(mptr + r);
            int sB = __ldg(mptr + r + 1);
            int eB = __ldg(mptr + r + 2);
            float vA, vB;
            row_pair(ment, sA, sB, sB, eB, hb, b, kh, vA, vB);
            vA += __shfl_xor_sync(0xffffffffu, vA, 16);
            vB += __shfl_xor_sync(0xffffffffu, vB, 16);
            a[jp * 2]     = vA;
            a[jp * 2 + 1] = vB;
        }
        if (kh == 0) {
            float4* o4 = reinterpret_cast<float4*>(outb + rb);
            o4[0] = make_float4(a[0],  a[1],  a[2],  a[3]);
            o4[1] = make_float4(a[4],  a[5],  a[6],  a[7]);
            o4[2] = make_float4(a[8],  a[9],  a[10], a[11]);
            o4[3] = make_float4(a[12], a[13], a[14], a[15]);
        }
    }
}

// ---------------------------------------------------------------------------
// Launch
// ---------------------------------------------------------------------------
extern "C" void kernel_launch(void* const* d_in, const int* in_sizes, int n_in,
                              void* d_out, int out_size) {
    const float* x   = (const float*)d_in[0];
    const int*   er0 = (const int*)d_in[1];
    const int*   ec0 = (const int*)d_in[2];
    const float* ev0 = (const float*)d_in[3];
    const int*   er1 = (const int*)d_in[4];
    const int*   ec1 = (const int*)d_in[5];
    const float* ev1 = (const float*)d_in[6];
    const int*   er2 = (const int*)d_in[7];
    const int*   ec2 = (const int*)d_in[8];
    const float* ev2 = (const float*)d_in[9];
    const int*   mr  = (const int*)d_in[10];
    const int*   mc  = (const int*)d_in[11];
    const float* mv  = (const float*)d_in[12];
    float* out = (float*)d_out;

    static int attr_done = 0;
    if (!attr_done) {
        cudaFuncSetAttribute(fused_k, cudaFuncAttributeMaxDynamicSharedMemorySize,
                             SMEM_BYTES);
        attr_done = 1;
    }

    build_k<<<4, BLD>>>(er0, ec0, ev0, er1, ec1, ev1, er2, ec2, ev2, mr, mc, mv);
    fused_k<<<NBLK, NTHR, SMEM_BYTES>>>(x, out);
}